// round 3
// baseline (speedup 1.0000x reference)
#include <cuda_runtime.h>
#include <math.h>

#define NN 512
#define CSd 384
#define CZd 128
#define PROJ 1152
#define FEAT 2112

__device__ __align__(16) float g_Wcat[CSd * PROJ];
__device__ __align__(16) float g_bcat[PROJ];
__device__ __align__(16) float g_proj[NN * PROJ];
__device__ __align__(16) float g_qg[NN * 144];
__device__ __align__(16) float g_kg[NN * 144];
__device__ __align__(16) float g_vg[NN * 288];
__device__ __align__(16) float g_qsq[NN * 12];
__device__ __align__(16) float g_ksq[NN * 12];
__device__ __align__(16) float g_bias[NN * NN * 12];
__device__ __align__(16) float g_attnT[12 * NN * NN];
__device__ __align__(16) float g_vpack[NN * 576];
__device__ __align__(16) float g_oval[NN * 576];
__device__ __align__(16) float g_feats[NN * FEAT];
__device__ __align__(16) float g_part[4 * NN * CSd];

// ------------------------------------------------ K0: pack projection weights
__global__ void pack_kernel(const float* Wq, const float* bq, const float* Wk, const float* bk,
                            const float* Wv, const float* bv, const float* Wqp, const float* bqp,
                            const float* Wkp, const float* bkp, const float* Wvp, const float* bvp) {
    int idx = blockIdx.x * blockDim.x + threadIdx.x;
    if (idx < CSd * PROJ) {
        int r = idx / PROJ, gc = idx % PROJ;
        const float* W; int w, lc;
        if      (gc < 192) { W = Wq;  w = 192; lc = gc;       }
        else if (gc < 384) { W = Wk;  w = 192; lc = gc - 192; }
        else if (gc < 576) { W = Wv;  w = 192; lc = gc - 384; }
        else if (gc < 720) { W = Wqp; w = 144; lc = gc - 576; }
        else if (gc < 864) { W = Wkp; w = 144; lc = gc - 720; }
        else               { W = Wvp; w = 288; lc = gc - 864; }
        g_Wcat[idx] = W[r * w + lc];
    }
    if (idx < PROJ) {
        int gc = idx; const float* bp; int lc;
        if      (gc < 192) { bp = bq;  lc = gc;       }
        else if (gc < 384) { bp = bk;  lc = gc - 192; }
        else if (gc < 576) { bp = bv;  lc = gc - 384; }
        else if (gc < 720) { bp = bqp; lc = gc - 576; }
        else if (gc < 864) { bp = bkp; lc = gc - 720; }
        else               { bp = bvp; lc = gc - 864; }
        g_bcat[idx] = bp[lc];
    }
}

#define FMA16(acc, a, b) do { \
    acc[0][0] += a.x*b.x; acc[0][1] += a.x*b.y; acc[0][2] += a.x*b.z; acc[0][3] += a.x*b.w; \
    acc[1][0] += a.y*b.x; acc[1][1] += a.y*b.y; acc[1][2] += a.y*b.z; acc[1][3] += a.y*b.w; \
    acc[2][0] += a.z*b.x; acc[2][1] += a.z*b.y; acc[2][2] += a.z*b.z; acc[2][3] += a.z*b.w; \
    acc[3][0] += a.w*b.x; acc[3][1] += a.w*b.y; acc[3][2] += a.w*b.z; acc[3][3] += a.w*b.w; \
} while (0)

// ------------------------------------------------ K1: s(512x384) @ Wcat(384x1152) + b
__global__ __launch_bounds__(256) void proj_gemm(const float* __restrict__ sIn) {
    __shared__ __align__(16) float As[32][68];
    __shared__ __align__(16) float Bs[32][68];
    int n0 = blockIdx.x * 64, c0 = blockIdx.y * 64;
    int tid = threadIdx.x, tx = tid % 16, ty = tid / 16;
    float acc[4][4] = {};
    for (int kt = 0; kt < 12; kt++) {
        int kb = kt * 32;
        for (int i = tid; i < 2048; i += 256)
            As[i % 32][i / 32] = sIn[(n0 + i / 32) * CSd + kb + (i % 32)];
        for (int i = tid; i < 2048; i += 256)
            Bs[i / 64][i % 64] = g_Wcat[(kb + i / 64) * PROJ + c0 + (i % 64)];
        __syncthreads();
        #pragma unroll
        for (int kk = 0; kk < 32; kk++) {
            float4 a = *(const float4*)&As[kk][ty * 4];
            float4 b = *(const float4*)&Bs[kk][tx * 4];
            FMA16(acc, a, b);
        }
        __syncthreads();
    }
    #pragma unroll
    for (int i = 0; i < 4; i++) {
        int row = n0 + ty * 4 + i;
        #pragma unroll
        for (int j = 0; j < 4; j++) {
            int col = c0 + tx * 4 + j;
            g_proj[(size_t)row * PROJ + col] = acc[i][j] + g_bcat[col];
        }
    }
}

// ------------------------------------------------ K2: rigid transform + squares + vpack
__global__ void geom_kernel(const float* __restrict__ trans, const float* __restrict__ rot) {
    int n = blockIdx.x, t = threadIdx.x;   // 128 threads
    __shared__ float R[9], T[3], qsq[12], ksq[12];
    if (t < 9)  R[t] = rot[n * 9 + t];
    if (t < 3)  T[t] = trans[n * 3 + t];
    if (t < 12) { qsq[t] = 0.f; ksq[t] = 0.f; }
    __syncthreads();
    const float* pr = g_proj + (size_t)n * PROJ;
    if (t < 48) {
        float x = pr[576 + t*3], y = pr[576 + t*3 + 1], zz = pr[576 + t*3 + 2];
        float gx = R[0]*x + R[1]*y + R[2]*zz + T[0];
        float gy = R[3]*x + R[4]*y + R[5]*zz + T[1];
        float gz = R[6]*x + R[7]*y + R[8]*zz + T[2];
        g_qg[n*144 + t*3] = gx; g_qg[n*144 + t*3 + 1] = gy; g_qg[n*144 + t*3 + 2] = gz;
        atomicAdd(&qsq[t >> 2], gx*gx + gy*gy + gz*gz);
    } else if (t < 96) {
        int u = t - 48;
        float x = pr[720 + u*3], y = pr[720 + u*3 + 1], zz = pr[720 + u*3 + 2];
        float gx = R[0]*x + R[1]*y + R[2]*zz + T[0];
        float gy = R[3]*x + R[4]*y + R[5]*zz + T[1];
        float gz = R[6]*x + R[7]*y + R[8]*zz + T[2];
        g_kg[n*144 + u*3] = gx; g_kg[n*144 + u*3 + 1] = gy; g_kg[n*144 + u*3 + 2] = gz;
        atomicAdd(&ksq[u >> 2], gx*gx + gy*gy + gz*gz);
    }
    if (t < 96) {
        float x = pr[864 + t*3], y = pr[864 + t*3 + 1], zz = pr[864 + t*3 + 2];
        g_vg[n*288 + t*3]     = R[0]*x + R[1]*y + R[2]*zz + T[0];
        g_vg[n*288 + t*3 + 1] = R[3]*x + R[4]*y + R[5]*zz + T[1];
        g_vg[n*288 + t*3 + 2] = R[6]*x + R[7]*y + R[8]*zz + T[2];
    }
    __syncthreads();
    if (t < 12) { g_qsq[n*12 + t] = qsq[t]; g_ksq[n*12 + t] = ksq[t]; }
    for (int i = t; i < 576; i += 128) {
        int h = i / 48, c = i % 48;
        float v = 0.f;
        if (c < 16)      v = pr[384 + h*16 + c];
        else if (c < 40) v = g_vg[n*288 + h*24 + (c - 16)];
        g_vpack[(size_t)n * 576 + i] = v;
    }
}

// ------------------------------------------------ K2b: bias[n][m][h] = z@Wb + bb + dist + multiscale
__global__ __launch_bounds__(256) void bias_kernel(const float* __restrict__ z,
        const float* __restrict__ trans, const float* __restrict__ Wb, const float* __restrict__ bb,
        const float* __restrict__ dist_emb, const float* __restrict__ scale_logits) {
    int n = blockIdx.x, tid = threadIdx.x;
    __shared__ __align__(16) float4 wT[12][32];    // wT[h][c4] = Wb[4c..4c+3][h]
    __shared__ float des[64 * 12], phs[36], bbs[12], Tn[3];
    for (int i = tid; i < 12 * 32; i += 256) {
        int h = i / 32, c4 = i % 32;
        wT[h][c4] = make_float4(Wb[(c4*4)*12 + h], Wb[(c4*4+1)*12 + h],
                                Wb[(c4*4+2)*12 + h], Wb[(c4*4+3)*12 + h]);
    }
    for (int i = tid; i < 768; i += 256) des[i] = dist_emb[i];
    if (tid < 12) {
        bbs[tid] = bb[tid];
        float e0 = expf(scale_logits[tid]), e1 = expf(scale_logits[12 + tid]), e2 = expf(scale_logits[24 + tid]);
        float inv = 1.f / (e0 + e1 + e2);
        phs[tid] = e0 * inv; phs[12 + tid] = e1 * inv; phs[24 + tid] = e2 * inv;
    }
    if (tid < 3) Tn[tid] = trans[n*3 + tid];
    __syncthreads();
    float acc[2][12];
    #pragma unroll
    for (int j = 0; j < 2; j++) {
        int m = tid + j * 256;
        float dx = Tn[0] - trans[m*3], dy = Tn[1] - trans[m*3+1], dz = Tn[2] - trans[m*3+2];
        float d = sqrtf(dx*dx + dy*dy + dz*dz);
        int bin = max(0, min(63, (int)ceilf(d * 2.f) - 1));
        float w0 = (d <= 5.f) ? 1.f : 0.f;
        float w1 = (d > 5.f && d <= 15.f) ? 1.f : 0.f;
        #pragma unroll
        for (int h = 0; h < 12; h++)
            acc[j][h] = bbs[h] + des[bin*12 + h] + w0*phs[h] + w1*phs[12 + h] + phs[24 + h];
    }
    const float4* z4 = (const float4*)z + (size_t)n * NN * 32;
    #pragma unroll 2
    for (int c4 = 0; c4 < 32; c4++) {
        float4 zv0 = z4[(size_t)tid * 32 + c4];
        float4 zv1 = z4[(size_t)(tid + 256) * 32 + c4];
        #pragma unroll
        for (int h = 0; h < 12; h++) {
            float4 w = wT[h][c4];
            acc[0][h] += zv0.x*w.x + zv0.y*w.y + zv0.z*w.z + zv0.w*w.w;
            acc[1][h] += zv1.x*w.x + zv1.y*w.y + zv1.z*w.z + zv1.w*w.w;
        }
    }
    #pragma unroll
    for (int j = 0; j < 2; j++) {
        float* bp = g_bias + ((size_t)n * NN + tid + j * 256) * 12;
        #pragma unroll
        for (int h = 0; h < 12; h++) bp[h] = acc[j][h];
    }
}

// ------------------------------------------------ K3: logits + softmax -> g_attnT[h][n][m]
__global__ __launch_bounds__(256) void attn_kernel(const float* __restrict__ head_weights) {
    int n0 = blockIdx.x * 2;
    int tid = threadIdx.x;
    __shared__ float qs[2][192], qgs[2][144], qsqs[2][12];
    __shared__ float hws[12];
    __shared__ float red[8 * 24];
    __shared__ float gmax[24], gsum[24];

    for (int i = tid; i < 2*192; i += 256) qs[i/192][i%192] = g_proj[(size_t)(n0 + i/192) * PROJ + (i%192)];
    for (int i = tid; i < 2*144; i += 256) qgs[i/144][i%144] = g_qg[(n0 + i/144) * 144 + (i%144)];
    if (tid < 24) qsqs[tid/12][tid%12] = g_qsq[(n0 + tid/12) * 12 + tid%12];
    if (tid < 12) hws[tid] = head_weights[tid];
    __syncthreads();

    float l[2][2][12];
    #pragma unroll
    for (int j = 0; j < 2; j++) {
        int m = tid + j * 256;
        const float* krow = g_proj + (size_t)m * PROJ + 192;
        const float* kgr  = g_kg + (size_t)m * 144;
        #pragma unroll
        for (int nn = 0; nn < 2; nn++) {
            const float* bp = g_bias + ((size_t)(n0 + nn) * NN + m) * 12;
            #pragma unroll
            for (int h = 0; h < 12; h++) l[nn][j][h] = bp[h];
        }
        #pragma unroll
        for (int h = 0; h < 12; h++) {
            float s0 = 0.f, s1 = 0.f;
            #pragma unroll
            for (int c = 0; c < 16; c++) {
                float kc = krow[h*16 + c];
                s0 += qs[0][h*16 + c] * kc;
                s1 += qs[1][h*16 + c] * kc;
            }
            float c0 = 0.f, c1 = 0.f;
            #pragma unroll
            for (int dd = 0; dd < 12; dd++) {
                float kg = kgr[h*12 + dd];
                c0 += qgs[0][h*12 + dd] * kg;
                c1 += qgs[1][h*12 + dd] * kg;
            }
            float ks = g_ksq[m*12 + h];
            l[0][j][h] += s0 * 0.25f - 0.5f * (qsqs[0][h] + ks - 2.f * c0) * hws[h];
            l[1][j][h] += s1 * 0.25f - 0.5f * (qsqs[1][h] + ks - 2.f * c1) * hws[h];
        }
    }
    int warp = tid >> 5, lane = tid & 31;
    #pragma unroll
    for (int nn = 0; nn < 2; nn++)
        #pragma unroll
        for (int h = 0; h < 12; h++) {
            float v = fmaxf(l[nn][0][h], l[nn][1][h]);
            #pragma unroll
            for (int o = 16; o; o >>= 1) v = fmaxf(v, __shfl_xor_sync(0xffffffffu, v, o));
            if (lane == 0) red[warp*24 + nn*12 + h] = v;
        }
    __syncthreads();
    if (tid < 24) {
        float mx = red[tid];
        for (int w = 1; w < 8; w++) mx = fmaxf(mx, red[w*24 + tid]);
        gmax[tid] = mx;
    }
    __syncthreads();
    #pragma unroll
    for (int nn = 0; nn < 2; nn++)
        #pragma unroll
        for (int h = 0; h < 12; h++) {
            float mx = gmax[nn*12 + h];
            l[nn][0][h] = expf(l[nn][0][h] - mx);
            l[nn][1][h] = expf(l[nn][1][h] - mx);
            float v = l[nn][0][h] + l[nn][1][h];
            #pragma unroll
            for (int o = 16; o; o >>= 1) v += __shfl_xor_sync(0xffffffffu, v, o);
            if (lane == 0) red[warp*24 + nn*12 + h] = v;
        }
    __syncthreads();
    if (tid < 24) {
        float sm = 0.f;
        for (int w = 0; w < 8; w++) sm += red[w*24 + tid];
        gsum[tid] = sm;
    }
    __syncthreads();
    #pragma unroll
    for (int nn = 0; nn < 2; nn++)
        #pragma unroll
        for (int h = 0; h < 12; h++) {
            float inv = 1.f / gsum[nn*12 + h];
            g_attnT[((size_t)h*NN + n0 + nn)*NN + tid]       = l[nn][0][h] * inv;
            g_attnT[((size_t)h*NN + n0 + nn)*NN + tid + 256] = l[nn][1][h] * inv;
        }
}

// ------------------------------------------------ K4a: per-head attn @ [v|v_g]  (512x48x512)
__global__ __launch_bounds__(256) void outval_gemm() {
    __shared__ __align__(16) float As[32][68];
    __shared__ float Bs[32][48];
    int n0 = blockIdx.x * 64, h = blockIdx.y;
    int tid = threadIdx.x, tx = tid % 16, ty = tid / 16;
    float acc[4][3] = {};
    for (int kt = 0; kt < 16; kt++) {
        int kb = kt * 32;
        for (int i = tid; i < 2048; i += 256)
            As[i % 32][i / 32] = g_attnT[((size_t)h*NN + n0 + i/32)*NN + kb + (i % 32)];
        for (int i = tid; i < 1536; i += 256)
            Bs[i / 48][i % 48] = g_vpack[(size_t)(kb + i/48) * 576 + h*48 + (i % 48)];
        __syncthreads();
        #pragma unroll
        for (int kk = 0; kk < 32; kk++) {
            float4 a = *(const float4*)&As[kk][ty * 4];
            float b0 = Bs[kk][tx*3], b1 = Bs[kk][tx*3+1], b2 = Bs[kk][tx*3+2];
            acc[0][0] += a.x*b0; acc[0][1] += a.x*b1; acc[0][2] += a.x*b2;
            acc[1][0] += a.y*b0; acc[1][1] += a.y*b1; acc[1][2] += a.y*b2;
            acc[2][0] += a.z*b0; acc[2][1] += a.z*b1; acc[2][2] += a.z*b2;
            acc[3][0] += a.w*b0; acc[3][1] += a.w*b1; acc[3][2] += a.w*b2;
        }
        __syncthreads();
    }
    #pragma unroll
    for (int i = 0; i < 4; i++)
        #pragma unroll
        for (int j = 0; j < 3; j++)
            g_oval[(size_t)(n0 + ty*4 + i) * 576 + h*48 + tx*3 + j] = acc[i][j];
}

// ------------------------------------------------ K4b: pair_feat = attn @ z  per n
__global__ __launch_bounds__(256) void pairfeat_kernel(const float* __restrict__ z) {
    __shared__ float sm[12288];   // first 6144: attn rows; then 8x1536 reduction
    int n = blockIdx.x, tid = threadIdx.x;
    int c4 = tid & 31, mp = tid >> 5;      // 8 m-partitions of 64
    for (int i = tid; i < 6144; i += 256)
        sm[i] = g_attnT[((size_t)(i/512)*NN + n)*NN + (i % 512)];
    __syncthreads();
    float acc[12][4] = {};
    const float4* z4 = (const float4*)z + (size_t)n * NN * 32;
    #pragma unroll 2
    for (int m = mp*64; m < mp*64 + 64; m++) {
        float4 zv = z4[(size_t)m * 32 + c4];
        #pragma unroll
        for (int h = 0; h < 12; h++) {
            float a = sm[h*512 + m];
            acc[h][0] += a*zv.x; acc[h][1] += a*zv.y; acc[h][2] += a*zv.z; acc[h][3] += a*zv.w;
        }
    }
    __syncthreads();
    #pragma unroll
    for (int h = 0; h < 12; h++)
        #pragma unroll
        for (int j = 0; j < 4; j++)
            sm[mp*1536 + h*128 + c4*4 + j] = acc[h][j];
    __syncthreads();
    for (int o = tid; o < 1536; o += 256) {
        float s = 0.f;
        #pragma unroll
        for (int p = 0; p < 8; p++) s += sm[p*1536 + o];
        int h = o >> 7, c = o & 127;
        g_feats[(size_t)n*FEAT + h*176 + 48 + c] = s;
    }
}

// ------------------------------------------------ K5: local frame + norms + scalar copy
__global__ void assemble_kernel(const float* __restrict__ trans, const float* __restrict__ rot) {
    int n = blockIdx.x, t = threadIdx.x;  // 288 threads
    __shared__ float R[9], T[3];
    if (t < 9) R[t] = rot[n*9 + t];
    if (t < 3) T[t] = trans[n*3 + t];
    __syncthreads();
    if (t < 96) {
        int h = t / 8, p = t % 8;
        const float* g = &g_oval[(size_t)n*576 + h*48 + 16 + p*3];
        float gx = g[0] - T[0], gy = g[1] - T[1], gz = g[2] - T[2];
        float lx = R[0]*gx + R[3]*gy + R[6]*gz;
        float ly = R[1]*gx + R[4]*gy + R[7]*gz;
        float lz = R[2]*gx + R[5]*gy + R[8]*gz;
        float* f = &g_feats[(size_t)n*FEAT + h*176];
        f[16 + p*3] = lx; f[16 + p*3 + 1] = ly; f[16 + p*3 + 2] = lz;
        f[40 + p] = sqrtf(lx*lx + ly*ly + lz*lz);
    } else if (t < 96 + 192) {
        int u = t - 96, h = u / 16, c = u % 16;
        g_feats[(size_t)n*FEAT + h*176 + c] = g_oval[(size_t)n*576 + h*48 + c];
    }
}

// ------------------------------------------------ K6: feats(512x2112) @ Wout(2112x384), split-K
__global__ __launch_bounds__(256) void final_gemm(const float* __restrict__ Wout) {
    __shared__ __align__(16) float As[32][68];
    __shared__ __align__(16) float Bs[32][68];
    int n0 = blockIdx.x * 64, c0 = blockIdx.y * 64, sp = blockIdx.z;
    int tid = threadIdx.x, tx = tid % 16, ty = tid / 16;
    int k0 = sp * 17, k1 = min(66, k0 + 17);
    float acc[4][4] = {};
    for (int kt = k0; kt < k1; kt++) {
        int kb = kt * 32;
        for (int i = tid; i < 2048; i += 256)
            As[i % 32][i / 32] = g_feats[(size_t)(n0 + i/32)*FEAT + kb + (i % 32)];
        for (int i = tid; i < 2048; i += 256)
            Bs[i / 64][i % 64] = Wout[(size_t)(kb + i/64)*CSd + c0 + (i % 64)];
        __syncthreads();
        #pragma unroll
        for (int kk = 0; kk < 32; kk++) {
            float4 a = *(const float4*)&As[kk][ty * 4];
            float4 b = *(const float4*)&Bs[kk][tx * 4];
            FMA16(acc, a, b);
        }
        __syncthreads();
    }
    #pragma unroll
    for (int i = 0; i < 4; i++)
        #pragma unroll
        for (int j = 0; j < 4; j++)
            g_part[(size_t)sp*NN*CSd + (n0 + ty*4 + i)*CSd + c0 + tx*4 + j] = acc[i][j];
}

__global__ void finalize_kernel(const float* __restrict__ bout, float* __restrict__ out) {
    int idx = blockIdx.x * blockDim.x + threadIdx.x;
    if (idx < NN * CSd) {
        int c = idx % CSd;
        out[idx] = bout[c] + g_part[idx] + g_part[NN*CSd + idx]
                 + g_part[2*NN*CSd + idx] + g_part[3*NN*CSd + idx];
    }
}

extern "C" void kernel_launch(void* const* d_in, const int* in_sizes, int n_in,
                              void* d_out, int out_size) {
    const float* s       = (const float*)d_in[0];
    const float* z       = (const float*)d_in[1];
    const float* trans   = (const float*)d_in[2];
    const float* rot     = (const float*)d_in[3];
    const float* Wq  = (const float*)d_in[5];  const float* bq  = (const float*)d_in[6];
    const float* Wk  = (const float*)d_in[7];  const float* bk  = (const float*)d_in[8];
    const float* Wv  = (const float*)d_in[9];  const float* bv  = (const float*)d_in[10];
    const float* Wqp = (const float*)d_in[11]; const float* bqp = (const float*)d_in[12];
    const float* Wkp = (const float*)d_in[13]; const float* bkp = (const float*)d_in[14];
    const float* Wvp = (const float*)d_in[15]; const float* bvp = (const float*)d_in[16];
    const float* Wb  = (const float*)d_in[17]; const float* bb  = (const float*)d_in[18];
    const float* dist_emb      = (const float*)d_in[19];
    const float* scale_logits  = (const float*)d_in[20];
    const float* head_weights  = (const float*)d_in[21];
    const float* Wout = (const float*)d_in[22];
    const float* bout = (const float*)d_in[23];
    float* out = (float*)d_out;

    pack_kernel<<<(CSd*PROJ + 255)/256, 256>>>(Wq,bq,Wk,bk,Wv,bv,Wqp,bqp,Wkp,bkp,Wvp,bvp);
    bias_kernel<<<NN, 256>>>(z, trans, Wb, bb, dist_emb, scale_logits);
    proj_gemm<<<dim3(8, 18), 256>>>(s);
    geom_kernel<<<NN, 128>>>(trans, rot);
    attn_kernel<<<NN/2, 256>>>(head_weights);
    outval_gemm<<<dim3(8, 12), 256>>>();
    pairfeat_kernel<<<NN, 256>>>(z);
    assemble_kernel<<<NN, 288>>>(trans, rot);
    final_gemm<<<dim3(8, 6, 4), 256>>>(Wout);
    finalize_kernel<<<(NN*CSd + 255)/256, 256>>>(bout, out);
}

// round 4
// speedup vs baseline: 1.9702x; 1.9702x over previous
#include <cuda_runtime.h>
#include <math.h>

#define NN 512
#define CSd 384
#define CZd 128
#define PROJ 1152
#define FEAT 2112

__device__ __align__(16) float g_Wcat[CSd * PROJ];
__device__ __align__(16) float g_bcat[PROJ];
__device__ __align__(16) float g_proj[NN * PROJ];
__device__ __align__(16) float g_qg[NN * 144];
__device__ __align__(16) float g_kg[NN * 144];
__device__ __align__(16) float g_vg[NN * 288];
__device__ __align__(16) float g_qsq[NN * 12];
__device__ __align__(16) float g_ksq[NN * 12];
__device__ __align__(16) float g_qh[12 * NN * 32];
__device__ __align__(16) float g_kh[12 * NN * 32];
__device__ __align__(16) float g_attnT[12 * NN * NN];   // bias -> logits -> attn
__device__ __align__(16) float g_vpack[NN * 576];
__device__ __align__(16) float g_oval[NN * 576];
__device__ __align__(16) float g_feats[NN * FEAT];
__device__ __align__(16) float g_part[4 * NN * CSd];

// ------------------------------------------------ K0: pack projection weights
__global__ void pack_kernel(const float* Wq, const float* bq, const float* Wk, const float* bk,
                            const float* Wv, const float* bv, const float* Wqp, const float* bqp,
                            const float* Wkp, const float* bkp, const float* Wvp, const float* bvp) {
    int idx = blockIdx.x * blockDim.x + threadIdx.x;
    if (idx < CSd * PROJ) {
        int r = idx / PROJ, gc = idx % PROJ;
        const float* W; int w, lc;
        if      (gc < 192) { W = Wq;  w = 192; lc = gc;       }
        else if (gc < 384) { W = Wk;  w = 192; lc = gc - 192; }
        else if (gc < 576) { W = Wv;  w = 192; lc = gc - 384; }
        else if (gc < 720) { W = Wqp; w = 144; lc = gc - 576; }
        else if (gc < 864) { W = Wkp; w = 144; lc = gc - 720; }
        else               { W = Wvp; w = 288; lc = gc - 864; }
        g_Wcat[idx] = W[r * w + lc];
    }
    if (idx < PROJ) {
        int gc = idx; const float* bp; int lc;
        if      (gc < 192) { bp = bq;  lc = gc;       }
        else if (gc < 384) { bp = bk;  lc = gc - 192; }
        else if (gc < 576) { bp = bv;  lc = gc - 384; }
        else if (gc < 720) { bp = bqp; lc = gc - 576; }
        else if (gc < 864) { bp = bkp; lc = gc - 720; }
        else               { bp = bvp; lc = gc - 864; }
        g_bcat[idx] = bp[lc];
    }
}

#define FMA16(acc, a, b) do { \
    acc[0][0] += a.x*b.x; acc[0][1] += a.x*b.y; acc[0][2] += a.x*b.z; acc[0][3] += a.x*b.w; \
    acc[1][0] += a.y*b.x; acc[1][1] += a.y*b.y; acc[1][2] += a.y*b.z; acc[1][3] += a.y*b.w; \
    acc[2][0] += a.z*b.x; acc[2][1] += a.z*b.y; acc[2][2] += a.z*b.z; acc[2][3] += a.z*b.w; \
    acc[3][0] += a.w*b.x; acc[3][1] += a.w*b.y; acc[3][2] += a.w*b.z; acc[3][3] += a.w*b.w; \
} while (0)

// ------------------------------------------------ K1: s(512x384) @ Wcat(384x1152) + b
__global__ __launch_bounds__(256) void proj_gemm(const float* __restrict__ sIn) {
    __shared__ __align__(16) float As[32][68];
    __shared__ __align__(16) float Bs[32][68];
    int n0 = blockIdx.x * 64, c0 = blockIdx.y * 64;
    int tid = threadIdx.x, tx = tid % 16, ty = tid / 16;
    float acc[4][4] = {};
    for (int kt = 0; kt < 12; kt++) {
        int kb = kt * 32;
        for (int i = tid; i < 2048; i += 256)
            As[i % 32][i / 32] = sIn[(n0 + i / 32) * CSd + kb + (i % 32)];
        for (int i = tid; i < 2048; i += 256)
            Bs[i / 64][i % 64] = g_Wcat[(kb + i / 64) * PROJ + c0 + (i % 64)];
        __syncthreads();
        #pragma unroll
        for (int kk = 0; kk < 32; kk++) {
            float4 a = *(const float4*)&As[kk][ty * 4];
            float4 b = *(const float4*)&Bs[kk][tx * 4];
            FMA16(acc, a, b);
        }
        __syncthreads();
    }
    #pragma unroll
    for (int i = 0; i < 4; i++) {
        int row = n0 + ty * 4 + i;
        #pragma unroll
        for (int j = 0; j < 4; j++) {
            int col = c0 + tx * 4 + j;
            g_proj[(size_t)row * PROJ + col] = acc[i][j] + g_bcat[col];
        }
    }
}

// ------------------------------------------------ K2: rigid transform + qh/kh pack + vpack
__global__ void geom_kernel(const float* __restrict__ trans, const float* __restrict__ rot,
                            const float* __restrict__ head_weights) {
    int n = blockIdx.x, t = threadIdx.x;   // 128 threads
    __shared__ float R[9], T[3], qsq[12], ksq[12], hws[12];
    if (t < 9)  R[t] = rot[n * 9 + t];
    if (t < 3)  T[t] = trans[n * 3 + t];
    if (t < 12) { qsq[t] = 0.f; ksq[t] = 0.f; hws[t] = head_weights[t]; }
    __syncthreads();
    const float* pr = g_proj + (size_t)n * PROJ;
    if (t < 48) {
        float x = pr[576 + t*3], y = pr[576 + t*3 + 1], zz = pr[576 + t*3 + 2];
        float gx = R[0]*x + R[1]*y + R[2]*zz + T[0];
        float gy = R[3]*x + R[4]*y + R[5]*zz + T[1];
        float gz = R[6]*x + R[7]*y + R[8]*zz + T[2];
        g_qg[n*144 + t*3] = gx; g_qg[n*144 + t*3 + 1] = gy; g_qg[n*144 + t*3 + 2] = gz;
        atomicAdd(&qsq[t >> 2], gx*gx + gy*gy + gz*gz);
    } else if (t < 96) {
        int u = t - 48;
        float x = pr[720 + u*3], y = pr[720 + u*3 + 1], zz = pr[720 + u*3 + 2];
        float gx = R[0]*x + R[1]*y + R[2]*zz + T[0];
        float gy = R[3]*x + R[4]*y + R[5]*zz + T[1];
        float gz = R[6]*x + R[7]*y + R[8]*zz + T[2];
        g_kg[n*144 + u*3] = gx; g_kg[n*144 + u*3 + 1] = gy; g_kg[n*144 + u*3 + 2] = gz;
        atomicAdd(&ksq[u >> 2], gx*gx + gy*gy + gz*gz);
    }
    if (t < 96) {
        float x = pr[864 + t*3], y = pr[864 + t*3 + 1], zz = pr[864 + t*3 + 2];
        g_vg[n*288 + t*3]     = R[0]*x + R[1]*y + R[2]*zz + T[0];
        g_vg[n*288 + t*3 + 1] = R[3]*x + R[4]*y + R[5]*zz + T[1];
        g_vg[n*288 + t*3 + 2] = R[6]*x + R[7]*y + R[8]*zz + T[2];
    }
    __syncthreads();
    if (t < 12) { g_qsq[n*12 + t] = qsq[t]; g_ksq[n*12 + t] = ksq[t]; }
    // pack qh/kh (K=32 padded, logits = qh . kh)
    for (int i = t; i < 384; i += 128) {
        int h = i / 32, c = i % 32;
        float hw = hws[h];
        float qv = 0.f, kv = 0.f;
        if (c < 16) {
            qv = 0.25f * pr[h*16 + c];
            kv = pr[192 + h*16 + c];
        } else if (c < 28) {
            qv = hw * g_qg[n*144 + h*12 + (c - 16)];
            kv = g_kg[n*144 + h*12 + (c - 16)];
        } else if (c == 28) {
            qv = -0.5f * hw * qsq[h];
            kv = 1.f;
        } else if (c == 29) {
            qv = -0.5f * hw;
            kv = ksq[h];
        }
        g_qh[((size_t)h*NN + n)*32 + c] = qv;
        g_kh[((size_t)h*NN + n)*32 + c] = kv;
    }
    // vpack[m][h*48 + c]: c<16 scalar v, 16..39 v_g, 40..47 zero pad
    for (int i = t; i < 576; i += 128) {
        int h = i / 48, c = i % 48;
        float v = 0.f;
        if (c < 16)      v = pr[384 + h*16 + c];
        else if (c < 40) v = g_vg[n*288 + h*24 + (c - 16)];
        g_vpack[(size_t)n * 576 + i] = v;
    }
}

// ------------------------------------------------ K2b: bias -> g_attnT[h][n][m]
__global__ __launch_bounds__(256) void bias_kernel(const float* __restrict__ z,
        const float* __restrict__ trans, const float* __restrict__ Wb, const float* __restrict__ bb,
        const float* __restrict__ dist_emb, const float* __restrict__ scale_logits) {
    int n = blockIdx.x, tid = threadIdx.x;
    __shared__ __align__(16) float4 wT[12][32];
    __shared__ float des[64 * 12], phs[36], bbs[12], Tn[3];
    for (int i = tid; i < 12 * 32; i += 256) {
        int h = i / 32, c4 = i % 32;
        wT[h][c4] = make_float4(Wb[(c4*4)*12 + h], Wb[(c4*4+1)*12 + h],
                                Wb[(c4*4+2)*12 + h], Wb[(c4*4+3)*12 + h]);
    }
    for (int i = tid; i < 768; i += 256) des[i] = dist_emb[i];
    if (tid < 12) {
        bbs[tid] = bb[tid];
        float e0 = expf(scale_logits[tid]), e1 = expf(scale_logits[12 + tid]), e2 = expf(scale_logits[24 + tid]);
        float inv = 1.f / (e0 + e1 + e2);
        phs[tid] = e0 * inv; phs[12 + tid] = e1 * inv; phs[24 + tid] = e2 * inv;
    }
    if (tid < 3) Tn[tid] = trans[n*3 + tid];
    __syncthreads();
    float acc[2][12];
    #pragma unroll
    for (int j = 0; j < 2; j++) {
        int m = tid + j * 256;
        float dx = Tn[0] - trans[m*3], dy = Tn[1] - trans[m*3+1], dz = Tn[2] - trans[m*3+2];
        float d = sqrtf(dx*dx + dy*dy + dz*dz);
        int bin = max(0, min(63, (int)ceilf(d * 2.f) - 1));
        float w0 = (d <= 5.f) ? 1.f : 0.f;
        float w1 = (d > 5.f && d <= 15.f) ? 1.f : 0.f;
        #pragma unroll
        for (int h = 0; h < 12; h++)
            acc[j][h] = bbs[h] + des[bin*12 + h] + w0*phs[h] + w1*phs[12 + h] + phs[24 + h];
    }
    const float4* z4 = (const float4*)z + (size_t)n * NN * 32;
    #pragma unroll 2
    for (int c4 = 0; c4 < 32; c4++) {
        float4 zv0 = z4[(size_t)tid * 32 + c4];
        float4 zv1 = z4[(size_t)(tid + 256) * 32 + c4];
        #pragma unroll
        for (int h = 0; h < 12; h++) {
            float4 w = wT[h][c4];
            acc[0][h] += zv0.x*w.x + zv0.y*w.y + zv0.z*w.z + zv0.w*w.w;
            acc[1][h] += zv1.x*w.x + zv1.y*w.y + zv1.z*w.z + zv1.w*w.w;
        }
    }
    #pragma unroll
    for (int h = 0; h < 12; h++) {
        g_attnT[((size_t)h*NN + n)*NN + tid]       = acc[0][h];
        g_attnT[((size_t)h*NN + n)*NN + tid + 256] = acc[1][h];
    }
}

// ------------------------------------------------ K3: logits GEMM  (per head, 512x512x32) += bias
__global__ __launch_bounds__(256) void logits_gemm() {
    __shared__ __align__(16) float As[32][68];
    __shared__ __align__(16) float Bs[32][68];
    int m0 = blockIdx.x * 64, n0 = blockIdx.y * 64, h = blockIdx.z;
    int tid = threadIdx.x, tx = tid % 16, ty = tid / 16;
    for (int i = tid; i < 2048; i += 256)
        As[i % 32][i / 32] = g_qh[((size_t)h*NN + n0 + i/32)*32 + (i % 32)];
    for (int i = tid; i < 2048; i += 256)
        Bs[i % 32][i / 32] = g_kh[((size_t)h*NN + m0 + i/32)*32 + (i % 32)];
    __syncthreads();
    float acc[4][4] = {};
    #pragma unroll
    for (int kk = 0; kk < 32; kk++) {
        float4 a = *(const float4*)&As[kk][ty * 4];
        float4 b = *(const float4*)&Bs[kk][tx * 4];
        FMA16(acc, a, b);
    }
    #pragma unroll
    for (int i = 0; i < 4; i++) {
        float* row = g_attnT + ((size_t)h*NN + n0 + ty*4 + i)*NN + m0;
        #pragma unroll
        for (int j = 0; j < 4; j++) {
            int m = tx*4 + j;
            row[m] += acc[i][j];
        }
    }
}

// ------------------------------------------------ K3b: softmax over m, in place
__global__ __launch_bounds__(256) void softmax_kernel() {
    int n = blockIdx.x, h = blockIdx.y;
    int tid = threadIdx.x, warp = tid >> 5, lane = tid & 31;
    __shared__ float red[8];
    float* row = g_attnT + ((size_t)h*NN + n)*NN;
    float v0 = row[tid], v1 = row[tid + 256];
    float mx = fmaxf(v0, v1);
    #pragma unroll
    for (int o = 16; o; o >>= 1) mx = fmaxf(mx, __shfl_xor_sync(0xffffffffu, mx, o));
    if (lane == 0) red[warp] = mx;
    __syncthreads();
    mx = red[0];
    #pragma unroll
    for (int w = 1; w < 8; w++) mx = fmaxf(mx, red[w]);
    v0 = expf(v0 - mx); v1 = expf(v1 - mx);
    float sm = v0 + v1;
    #pragma unroll
    for (int o = 16; o; o >>= 1) sm += __shfl_xor_sync(0xffffffffu, sm, o);
    __syncthreads();
    if (lane == 0) red[warp] = sm;
    __syncthreads();
    sm = 0.f;
    #pragma unroll
    for (int w = 0; w < 8; w++) sm += red[w];
    float inv = 1.f / sm;
    row[tid] = v0 * inv;
    row[tid + 256] = v1 * inv;
}

// ------------------------------------------------ K4a: per-head attn @ [v|v_g]  (512x48x512)
__global__ __launch_bounds__(256) void outval_gemm() {
    __shared__ __align__(16) float As[32][68];
    __shared__ float Bs[32][48];
    int n0 = blockIdx.x * 64, h = blockIdx.y;
    int tid = threadIdx.x, tx = tid % 16, ty = tid / 16;
    float acc[4][3] = {};
    for (int kt = 0; kt < 16; kt++) {
        int kb = kt * 32;
        for (int i = tid; i < 2048; i += 256)
            As[i % 32][i / 32] = g_attnT[((size_t)h*NN + n0 + i/32)*NN + kb + (i % 32)];
        for (int i = tid; i < 1536; i += 256)
            Bs[i / 48][i % 48] = g_vpack[(size_t)(kb + i/48) * 576 + h*48 + (i % 48)];
        __syncthreads();
        #pragma unroll
        for (int kk = 0; kk < 32; kk++) {
            float4 a = *(const float4*)&As[kk][ty * 4];
            float b0 = Bs[kk][tx*3], b1 = Bs[kk][tx*3+1], b2 = Bs[kk][tx*3+2];
            acc[0][0] += a.x*b0; acc[0][1] += a.x*b1; acc[0][2] += a.x*b2;
            acc[1][0] += a.y*b0; acc[1][1] += a.y*b1; acc[1][2] += a.y*b2;
            acc[2][0] += a.z*b0; acc[2][1] += a.z*b1; acc[2][2] += a.z*b2;
            acc[3][0] += a.w*b0; acc[3][1] += a.w*b1; acc[3][2] += a.w*b2;
        }
        __syncthreads();
    }
    #pragma unroll
    for (int i = 0; i < 4; i++)
        #pragma unroll
        for (int j = 0; j < 3; j++)
            g_oval[(size_t)(n0 + ty*4 + i) * 576 + h*48 + tx*3 + j] = acc[i][j];
}

// ------------------------------------------------ K4b: pair_feat = attn @ z  per n
__global__ __launch_bounds__(256) void pairfeat_kernel(const float* __restrict__ z) {
    __shared__ float sm[12288];
    int n = blockIdx.x, tid = threadIdx.x;
    int c4 = tid & 31, mp = tid >> 5;
    for (int i = tid; i < 6144; i += 256)
        sm[i] = g_attnT[((size_t)(i/512)*NN + n)*NN + (i % 512)];
    __syncthreads();
    float acc[12][4] = {};
    const float4* z4 = (const float4*)z + (size_t)n * NN * 32;
    #pragma unroll 2
    for (int m = mp*64; m < mp*64 + 64; m++) {
        float4 zv = z4[(size_t)m * 32 + c4];
        #pragma unroll
        for (int h = 0; h < 12; h++) {
            float a = sm[h*512 + m];
            acc[h][0] += a*zv.x; acc[h][1] += a*zv.y; acc[h][2] += a*zv.z; acc[h][3] += a*zv.w;
        }
    }
    __syncthreads();
    #pragma unroll
    for (int h = 0; h < 12; h++)
        #pragma unroll
        for (int j = 0; j < 4; j++)
            sm[mp*1536 + h*128 + c4*4 + j] = acc[h][j];
    __syncthreads();
    for (int o = tid; o < 1536; o += 256) {
        float s = 0.f;
        #pragma unroll
        for (int p = 0; p < 8; p++) s += sm[p*1536 + o];
        int h = o >> 7, c = o & 127;
        g_feats[(size_t)n*FEAT + h*176 + 48 + c] = s;
    }
}

// ------------------------------------------------ K5: local frame + norms + scalar copy
__global__ void assemble_kernel(const float* __restrict__ trans, const float* __restrict__ rot) {
    int n = blockIdx.x, t = threadIdx.x;  // 288 threads
    __shared__ float R[9], T[3];
    if (t < 9) R[t] = rot[n*9 + t];
    if (t < 3) T[t] = trans[n*3 + t];
    __syncthreads();
    if (t < 96) {
        int h = t / 8, p = t % 8;
        const float* g = &g_oval[(size_t)n*576 + h*48 + 16 + p*3];
        float gx = g[0] - T[0], gy = g[1] - T[1], gz = g[2] - T[2];
        float lx = R[0]*gx + R[3]*gy + R[6]*gz;
        float ly = R[1]*gx + R[4]*gy + R[7]*gz;
        float lz = R[2]*gx + R[5]*gy + R[8]*gz;
        float* f = &g_feats[(size_t)n*FEAT + h*176];
        f[16 + p*3] = lx; f[16 + p*3 + 1] = ly; f[16 + p*3 + 2] = lz;
        f[40 + p] = sqrtf(lx*lx + ly*ly + lz*lz);
    } else if (t < 96 + 192) {
        int u = t - 96, h = u / 16, c = u % 16;
        g_feats[(size_t)n*FEAT + h*176 + c] = g_oval[(size_t)n*576 + h*48 + c];
    }
}

// ------------------------------------------------ K6: feats(512x2112) @ Wout(2112x384), split-K
__global__ __launch_bounds__(256) void final_gemm(const float* __restrict__ Wout) {
    __shared__ __align__(16) float As[32][68];
    __shared__ __align__(16) float Bs[32][68];
    int n0 = blockIdx.x * 64, c0 = blockIdx.y * 64, sp = blockIdx.z;
    int tid = threadIdx.x, tx = tid % 16, ty = tid / 16;
    int k0 = sp * 17, k1 = min(66, k0 + 17);
    float acc[4][4] = {};
    for (int kt = k0; kt < k1; kt++) {
        int kb = kt * 32;
        for (int i = tid; i < 2048; i += 256)
            As[i % 32][i / 32] = g_feats[(size_t)(n0 + i/32)*FEAT + kb + (i % 32)];
        for (int i = tid; i < 2048; i += 256)
            Bs[i / 64][i % 64] = Wout[(size_t)(kb + i/64)*CSd + c0 + (i % 64)];
        __syncthreads();
        #pragma unroll
        for (int kk = 0; kk < 32; kk++) {
            float4 a = *(const float4*)&As[kk][ty * 4];
            float4 b = *(const float4*)&Bs[kk][tx * 4];
            FMA16(acc, a, b);
        }
        __syncthreads();
    }
    #pragma unroll
    for (int i = 0; i < 4; i++)
        #pragma unroll
        for (int j = 0; j < 4; j++)
            g_part[(size_t)sp*NN*CSd + (n0 + ty*4 + i)*CSd + c0 + tx*4 + j] = acc[i][j];
}

__global__ void finalize_kernel(const float* __restrict__ bout, float* __restrict__ out) {
    int idx = blockIdx.x * blockDim.x + threadIdx.x;
    if (idx < NN * CSd) {
        int c = idx % CSd;
        out[idx] = bout[c] + g_part[idx] + g_part[NN*CSd + idx]
                 + g_part[2*NN*CSd + idx] + g_part[3*NN*CSd + idx];
    }
}

extern "C" void kernel_launch(void* const* d_in, const int* in_sizes, int n_in,
                              void* d_out, int out_size) {
    const float* s       = (const float*)d_in[0];
    const float* z       = (const float*)d_in[1];
    const float* trans   = (const float*)d_in[2];
    const float* rot     = (const float*)d_in[3];
    const float* Wq  = (const float*)d_in[5];  const float* bq  = (const float*)d_in[6];
    const float* Wk  = (const float*)d_in[7];  const float* bk  = (const float*)d_in[8];
    const float* Wv  = (const float*)d_in[9];  const float* bv  = (const float*)d_in[10];
    const float* Wqp = (const float*)d_in[11]; const float* bqp = (const float*)d_in[12];
    const float* Wkp = (const float*)d_in[13]; const float* bkp = (const float*)d_in[14];
    const float* Wvp = (const float*)d_in[15]; const float* bvp = (const float*)d_in[16];
    const float* Wb  = (const float*)d_in[17]; const float* bb  = (const float*)d_in[18];
    const float* dist_emb      = (const float*)d_in[19];
    const float* scale_logits  = (const float*)d_in[20];
    const float* head_weights  = (const float*)d_in[21];
    const float* Wout = (const float*)d_in[22];
    const float* bout = (const float*)d_in[23];
    float* out = (float*)d_out;

    pack_kernel<<<(CSd*PROJ + 255)/256, 256>>>(Wq,bq,Wk,bk,Wv,bv,Wqp,bqp,Wkp,bkp,Wvp,bvp);
    bias_kernel<<<NN, 256>>>(z, trans, Wb, bb, dist_emb, scale_logits);
    proj_gemm<<<dim3(8, 18), 256>>>(s);
    geom_kernel<<<NN, 128>>>(trans, rot, head_weights);
    logits_gemm<<<dim3(8, 8, 12), 256>>>();
    softmax_kernel<<<dim3(NN, 12), 256>>>();
    outval_gemm<<<dim3(8, 12), 256>>>();
    pairfeat_kernel<<<NN, 256>>>(z);
    assemble_kernel<<<NN, 288>>>(trans, rot);
    final_gemm<<<dim3(8, 6, 4), 256>>>(Wout);
    finalize_kernel<<<(NN*CSd + 255)/256, 256>>>(bout, out);
}